// round 2
// baseline (speedup 1.0000x reference)
#include <cuda_runtime.h>
#include <cuda_bf16.h>

#define KS   5
#define K2   25      // KS*KS
#define C1   32      // hidden 1
#define C2   64      // hidden 2
#define NG   64      // graphs
#define NMAX 20000

// ---------------- scratch (device globals; no allocations) ----------------
__device__ float        g_T[NMAX * K2];        // layer-1 basis-weighted scalar accum
__device__ float        g_deg[NMAX];           // in-degree
__device__ float        g_h1[NMAX * C1];       // layer-1 output fp32 (for root2 term)
__device__ unsigned int g_h1b[NMAX * 16];      // layer-1 output bf16x2 packed (c pairs)
__device__ unsigned int g_Sb[NMAX * 400];      // layer-2 accum, bf16x2 [N][25][16]  (32MB)
__device__ float        g_C[NMAX * C2];        // GEMM output
__device__ float        g_pool[NG * C2];
__device__ float        g_cnt[NG];

// ---------------- f32x2 packed FMA helpers ----------------
#define PACK_F32X2(out, lo, hi) \
    asm("mov.b64 %0, {%1, %2};" : "=l"(out) : "f"(lo), "f"(hi))
#define UNPACK_F32X2(lo, hi, in) \
    asm("mov.b64 {%0, %1}, %2;" : "=f"(lo), "=f"(hi) : "l"(in))
#define FMA_F32X2(acc, a, b) \
    asm("fma.rn.f32x2 %0, %1, %2, %0;" : "+l"(acc) : "l"(a), "l"(b))

__device__ __forceinline__ void red_bf162(unsigned int* addr, unsigned int v) {
    asm volatile("red.global.add.noftz.bf16x2 [%0], %1;" :: "l"(addr), "r"(v) : "memory");
}

// ---------------- degree-1 B-spline basis (DIM=2, KS=5) ----------------
__device__ __forceinline__ void basis2(float a0, float a1, int* wi, float* bw) {
    float v0 = a0 * (KS - 1), v1 = a1 * (KS - 1);
    int k0 = (int)floorf(v0); k0 = min(max(k0, 0), KS - 2);
    int k1 = (int)floorf(v1); k1 = min(max(k1, 0), KS - 2);
    float f0 = v0 - (float)k0, f1 = v1 - (float)k1;
    float g0 = 1.f - f0, g1 = 1.f - f1;
    wi[0] = k0     + KS *  k1;      bw[0] = g0 * g1;
    wi[1] = k0 + 1 + KS *  k1;      bw[1] = f0 * g1;
    wi[2] = k0     + KS * (k1 + 1); bw[2] = g0 * f1;
    wi[3] = k0 + 1 + KS * (k1 + 1); bw[3] = f0 * f1;
}

// ---------------- zero scratch ----------------
__global__ void k_zero(int N) {
    long tid = (long)blockIdx.x * blockDim.x + threadIdx.x;
    long stride = (long)gridDim.x * blockDim.x;
    long nS4 = (long)N * 100;               // N*400 u32 / 4
    uint4* S4 = (uint4*)g_Sb;
    uint4 z4 = make_uint4(0u, 0u, 0u, 0u);
    for (long i = tid; i < nS4; i += stride) S4[i] = z4;
    long nT = (long)N * K2;
    for (long i = tid; i < nT; i += stride) g_T[i] = 0.f;
    for (long i = tid; i < N; i += stride) g_deg[i] = 0.f;
    for (long i = tid; i < NG * C2; i += stride) g_pool[i] = 0.f;
    for (long i = tid; i < NG; i += stride) g_cnt[i] = 0.f;
}

// ---------------- edge pass 1: T[dst][wi] += b * x[src]; deg ----------------
__global__ void k_edge1(const float* __restrict__ x, const float* __restrict__ ea,
                        const int* __restrict__ src, const int* __restrict__ dst, int E) {
    int e = blockIdx.x * blockDim.x + threadIdx.x;
    if (e >= E) return;
    int wi[4]; float bw[4];
    float2 eav = ((const float2*)ea)[e];
    basis2(eav.x, eav.y, wi, bw);
    float xs = x[src[e]];
    int d = dst[e];
    float* Tp = g_T + d * K2;
#pragma unroll
    for (int i = 0; i < 4; i++) atomicAdd(Tp + wi[i], bw[i] * xs);
    atomicAdd(g_deg + d, 1.f);
}

// ---------------- layer-1 node update: h1 = relu(T@W1/deg + x*root1 + b1) ----------------
__global__ void k_h1(const float* __restrict__ x, const float* __restrict__ W1,
                     const float* __restrict__ root1, const float* __restrict__ b1, int N) {
    int t = blockIdx.x * blockDim.x + threadIdx.x;
    if (t >= N * 16) return;
    int n = t >> 4, c2 = t & 15;
    const float* Tp = g_T + n * K2;
    float a0 = 0.f, a1 = 0.f;
#pragma unroll
    for (int w = 0; w < K2; w++) {
        float tv = Tp[w];
        a0 += tv * W1[w * C1 + 2 * c2];
        a1 += tv * W1[w * C1 + 2 * c2 + 1];
    }
    float dinv = 1.f / fmaxf(g_deg[n], 1.f);
    float xn = x[n];
    float h0 = fmaxf(a0 * dinv + xn * root1[2 * c2]     + b1[2 * c2],     0.f);
    float h1 = fmaxf(a1 * dinv + xn * root1[2 * c2 + 1] + b1[2 * c2 + 1], 0.f);
    g_h1[n * C1 + 2 * c2]     = h0;
    g_h1[n * C1 + 2 * c2 + 1] = h1;
    __nv_bfloat162 hb = __float22bfloat162_rn(make_float2(h0, h1));
    g_h1b[t] = *(unsigned int*)&hb;
}

// ---------------- edge pass 2: S[dst][wi][:] += b * h1[src][:]  (half-warp/edge, bf16x2) ----------------
__global__ void k_edge2(const float* __restrict__ ea,
                        const int* __restrict__ src, const int* __restrict__ dst, int E) {
    int gt = blockIdx.x * blockDim.x + threadIdx.x;
    int lane = gt & 31;
    int warp = gt >> 5;
    int e = warp * 2 + (lane >> 4);
    int hl = lane & 15;
    if (e >= E) return;
    int s = src[e], d = dst[e];
    float2 eav = ((const float2*)ea)[e];
    int wi[4]; float bw[4];
    basis2(eav.x, eav.y, wi, bw);
    float2 h = __bfloat1622float2(*(__nv_bfloat162*)&g_h1b[s * 16 + hl]);
    unsigned int* base = g_Sb + d * 400 + hl;
#pragma unroll
    for (int i = 0; i < 4; i++) {
        __nv_bfloat162 v = __float22bfloat162_rn(make_float2(bw[i] * h.x, bw[i] * h.y));
        red_bf162(base + wi[i] * 16, *(unsigned int*)&v);
    }
}

// ---------------- GEMM: C[N,64] = S[N,800](bf16) @ W2[800,64]  (f32x2 packed FMA) ----------------
// 32x64 tile, 128 threads, per-thread 2 rows x 8 cols (4 col-pairs)
__global__ void k_gemm(const float* __restrict__ W2, int N) {
    __shared__ float As[16][34];   // [k][row], padded to keep float2 reads 8B-aligned
    __shared__ float Bs[16][64];
    int tid = threadIdx.x;                 // 128
    int tx = tid & 7, ty = tid >> 3;       // tx: col-group (8 cols), ty: row-group (2 rows)
    int rowBase = blockIdx.x * 32;

    unsigned long long acc[2][4];
#pragma unroll
    for (int i = 0; i < 2; i++)
#pragma unroll
        for (int j = 0; j < 4; j++) acc[i][j] = 0ull;

    int ar = tid >> 2, akq = (tid & 3) * 4;     // A loader: row, k-offset (4 bf16)
    int bkr = tid >> 3, bc = (tid & 7) * 8;     // B loader: k-row, 8 cols

    for (int kt = 0; kt < K2 * C1; kt += 16) {
        // A tile: 32 rows x 16 k, bf16 -> fp32 transposed into As[k][row]
        int grow = rowBase + ar;
        uint2 av = make_uint2(0u, 0u);
        if (grow < N) av = *(const uint2*)&g_Sb[grow * 400 + ((kt + akq) >> 1)];
        float2 f0 = __bfloat1622float2(*(__nv_bfloat162*)&av.x);
        float2 f1 = __bfloat1622float2(*(__nv_bfloat162*)&av.y);
        As[akq + 0][ar] = f0.x; As[akq + 1][ar] = f0.y;
        As[akq + 2][ar] = f1.x; As[akq + 3][ar] = f1.y;
        // B tile: 16 x 64 fp32
        const float* wp = W2 + (kt + bkr) * 64 + bc;
        *(float4*)&Bs[bkr][bc]     = *(const float4*)wp;
        *(float4*)&Bs[bkr][bc + 4] = *(const float4*)(wp + 4);
        __syncthreads();
#pragma unroll
        for (int kk = 0; kk < 16; kk++) {
            float2 a = *(float2*)&As[kk][ty * 2];
            unsigned long long a0d, a1d;
            PACK_F32X2(a0d, a.x, a.x);
            PACK_F32X2(a1d, a.y, a.y);
            float4 b0 = *(float4*)&Bs[kk][tx * 8];
            float4 b1 = *(float4*)&Bs[kk][tx * 8 + 4];
            unsigned long long bp[4];
            PACK_F32X2(bp[0], b0.x, b0.y);
            PACK_F32X2(bp[1], b0.z, b0.w);
            PACK_F32X2(bp[2], b1.x, b1.y);
            PACK_F32X2(bp[3], b1.z, b1.w);
#pragma unroll
            for (int j = 0; j < 4; j++) {
                FMA_F32X2(acc[0][j], a0d, bp[j]);
                FMA_F32X2(acc[1][j], a1d, bp[j]);
            }
        }
        __syncthreads();
    }
#pragma unroll
    for (int i = 0; i < 2; i++) {
        int row = rowBase + ty * 2 + i;
        if (row < N) {
            float o[8];
#pragma unroll
            for (int j = 0; j < 4; j++) UNPACK_F32X2(o[2 * j], o[2 * j + 1], acc[i][j]);
            *(float4*)&g_C[row * C2 + tx * 8]     = make_float4(o[0], o[1], o[2], o[3]);
            *(float4*)&g_C[row * C2 + tx * 8 + 4] = make_float4(o[4], o[5], o[6], o[7]);
        }
    }
}

// ---------------- layer-2 node update + graph pooling ----------------
__global__ void k_h2pool(const float* __restrict__ root2, const float* __restrict__ b2,
                         const int* __restrict__ batch, int N) {
    int tid = threadIdx.x;               // 256 -> 4 nodes/block
    int n = blockIdx.x * 4 + (tid >> 6);
    int o = tid & 63;
    if (n >= N) return;
    float acc = g_C[n * C2 + o] / fmaxf(g_deg[n], 1.f) + b2[o];
    const float* hp = g_h1 + n * C1;
#pragma unroll
    for (int k = 0; k < C1; k++) acc += hp[k] * root2[k * C2 + o];
    float h = fmaxf(acc, 0.f);
    int b = batch[n];
    atomicAdd(&g_pool[b * C2 + o], h);
    if (o == 0) atomicAdd(&g_cnt[b], 1.f);
}

// ---------------- head MLP + log_softmax (one block per graph) ----------------
__global__ void k_mlp(const float* __restrict__ Wf1, const float* __restrict__ bf1,
                      const float* __restrict__ Wf2, const float* __restrict__ bf2,
                      float* __restrict__ out) {
    int b = blockIdx.x;
    int j = threadIdx.x;            // 128 threads
    __shared__ float gs[C2];
    __shared__ float ts[128];
    __shared__ float lg[10];
    if (j < C2) gs[j] = g_pool[b * C2 + j] / fmaxf(g_cnt[b], 1.f);
    __syncthreads();
    float t = bf1[j];
#pragma unroll
    for (int k = 0; k < C2; k++) t += gs[k] * Wf1[k * 128 + j];
    ts[j] = fmaxf(t, 0.f);
    __syncthreads();
    if (j < 10) {
        float a = bf2[j];
#pragma unroll
        for (int q = 0; q < 128; q++) a += ts[q] * Wf2[q * 10 + j];
        lg[j] = a;
    }
    __syncthreads();
    if (j == 0) {
        float m = lg[0];
#pragma unroll
        for (int q = 1; q < 10; q++) m = fmaxf(m, lg[q]);
        float s = 0.f;
#pragma unroll
        for (int q = 0; q < 10; q++) s += expf(lg[q] - m);
        float l = logf(s) + m;
#pragma unroll
        for (int q = 0; q < 10; q++) out[b * 10 + q] = lg[q] - l;
    }
}

// ---------------- launch ----------------
extern "C" void kernel_launch(void* const* d_in, const int* in_sizes, int n_in,
                              void* d_out, int out_size) {
    const float* x     = (const float*)d_in[0];
    const float* ea    = (const float*)d_in[1];
    const float* W1    = (const float*)d_in[2];
    const float* root1 = (const float*)d_in[3];
    const float* b1    = (const float*)d_in[4];
    const float* W2    = (const float*)d_in[5];
    const float* root2 = (const float*)d_in[6];
    const float* b2    = (const float*)d_in[7];
    const float* Wf1   = (const float*)d_in[8];
    const float* bf1   = (const float*)d_in[9];
    const float* Wf2   = (const float*)d_in[10];
    const float* bf2   = (const float*)d_in[11];
    const int*   ei    = (const int*)d_in[12];
    const int*   batch = (const int*)d_in[13];

    int N = in_sizes[0];        // Cin = 1 -> x has N elements
    int E = in_sizes[1] / 2;    // edge_attr is [E,2]
    const int* src = ei;
    const int* dst = ei + E;
    float* out = (float*)d_out;

    k_zero<<<2048, 256>>>(N);
    k_edge1<<<(E + 255) / 256, 256>>>(x, ea, src, dst, E);
    k_h1<<<(N * 16 + 255) / 256, 256>>>(x, W1, root1, b1, N);
    // one half-warp (16 lanes) per edge -> 16 threads/edge
    k_edge2<<<(E * 16 + 255) / 256, 256>>>(ea, src, dst, E);
    k_gemm<<<(N + 31) / 32, 128>>>(W2, N);
    k_h2pool<<<(N + 3) / 4, 256>>>(root2, b2, batch, N);
    k_mlp<<<NG, 128>>>(Wf1, bf1, Wf2, bf2, out);
}

// round 4
// speedup vs baseline: 1.8909x; 1.8909x over previous
#include <cuda_runtime.h>
#include <cuda_bf16.h>
#include <cstdint>

#define KS   5
#define K2   25
#define C1   32
#define C2   64
#define NG   64
#define NMAX 20000
#define KTOT 800

// ---------------- scratch (device globals; no allocations) ----------------
__device__ float        g_T[NMAX * K2];
__device__ float        g_deg[NMAX];
__device__ float        g_dinv[NMAX];
__device__ unsigned int g_h1b[NMAX * 16];     // h1 bf16x2 packed [N][16]
__device__ unsigned int g_Sb[NMAX * 400];     // S accum bf16x2 [N][25][16] (32MB)
__device__ uint2        g_W2f[56 * 8 * 32];   // B fragments: [kstep][ngroup][lane] (+root2 at 52-53)
__device__ float        g_pool[NG * C2];
__device__ float        g_cnt[NG];

// ---------------- helpers ----------------
__device__ __forceinline__ uint32_t smem_u32(const void* p) {
    uint32_t a;
    asm("{ .reg .u64 t; cvta.to.shared.u64 t, %1; cvt.u32.u64 %0, t; }" : "=r"(a) : "l"(p));
    return a;
}
__device__ __forceinline__ void red_bf162(unsigned int* addr, unsigned int v) {
    asm volatile("red.global.add.noftz.bf16x2 [%0], %1;" :: "l"(addr), "r"(v) : "memory");
}
__device__ __forceinline__ void red_f32(float* addr, float v) {
    asm volatile("red.global.add.f32 [%0], %1;" :: "l"(addr), "f"(v) : "memory");
}
__device__ __forceinline__ uint32_t scale_bf162(uint32_t v, float s) {
    float2 f = __bfloat1622float2(*(__nv_bfloat162*)&v);
    __nv_bfloat162 r = __float22bfloat162_rn(make_float2(f.x * s, f.y * s));
    return *(uint32_t*)&r;
}
__device__ __forceinline__ void ldmatrix_x4(uint32_t& a0, uint32_t& a1, uint32_t& a2,
                                            uint32_t& a3, uint32_t addr) {
    asm volatile("ldmatrix.sync.aligned.m8n8.x4.shared.b16 {%0,%1,%2,%3}, [%4];"
                 : "=r"(a0), "=r"(a1), "=r"(a2), "=r"(a3) : "r"(addr));
}
__device__ __forceinline__ void mma_bf16(float* c, uint32_t a0, uint32_t a1, uint32_t a2,
                                         uint32_t a3, uint32_t b0, uint32_t b1) {
    asm volatile(
        "mma.sync.aligned.m16n8k16.row.col.f32.bf16.bf16.f32 "
        "{%0,%1,%2,%3}, {%4,%5,%6,%7}, {%8,%9}, {%0,%1,%2,%3};"
        : "+f"(c[0]), "+f"(c[1]), "+f"(c[2]), "+f"(c[3])
        : "r"(a0), "r"(a1), "r"(a2), "r"(a3), "r"(b0), "r"(b1));
}

// ---------------- basis ----------------
__device__ __forceinline__ void basis2(float a0, float a1, int* wi, float* bw) {
    float v0 = a0 * (KS - 1), v1 = a1 * (KS - 1);
    int k0 = (int)floorf(v0); k0 = min(max(k0, 0), KS - 2);
    int k1 = (int)floorf(v1); k1 = min(max(k1, 0), KS - 2);
    float f0 = v0 - (float)k0, f1 = v1 - (float)k1;
    float g0 = 1.f - f0, g1 = 1.f - f1;
    wi[0] = k0     + KS *  k1;      bw[0] = g0 * g1;
    wi[1] = k0 + 1 + KS *  k1;      bw[1] = f0 * g1;
    wi[2] = k0     + KS * (k1 + 1); bw[2] = g0 * f1;
    wi[3] = k0 + 1 + KS * (k1 + 1); bw[3] = f0 * f1;
}

// ---------------- zero scratch ----------------
__global__ void k_zero(int N) {
    long tid = (long)blockIdx.x * blockDim.x + threadIdx.x;
    long stride = (long)gridDim.x * blockDim.x;
    long nS4 = (long)N * 100;
    uint4* S4 = (uint4*)g_Sb;
    uint4 z4 = make_uint4(0u, 0u, 0u, 0u);
    for (long i = tid; i < nS4; i += stride) S4[i] = z4;
    long nT = (long)N * K2;
    for (long i = tid; i < nT; i += stride) g_T[i] = 0.f;
    for (long i = tid; i < N; i += stride) g_deg[i] = 0.f;
    for (long i = tid; i < NG * C2; i += stride) g_pool[i] = 0.f;
    for (long i = tid; i < NG; i += stride) g_cnt[i] = 0.f;
}

// ---------------- prep B fragments: W2[800][64] + root2[32][64] -> mma frag order ----------------
__global__ void k_prepB(const float* __restrict__ W2, const float* __restrict__ root2) {
    int t = blockIdx.x * blockDim.x + threadIdx.x;
    if (t >= 56 * 8 * 32) return;
    int lane = t & 31, ng = (t >> 5) & 7, sg = t >> 8;
    int gid = lane >> 2, tig = lane & 3;
    int n = ng * 8 + gid;
    int k = sg * 16 + tig * 2;
    float f0 = 0.f, f1 = 0.f, f2 = 0.f, f3 = 0.f;
    if (sg < 50) {                       // W2 region: k in [0,800)
        f0 = W2[k * C2 + n];       f1 = W2[(k + 1) * C2 + n];
        f2 = W2[(k + 8) * C2 + n]; f3 = W2[(k + 9) * C2 + n];
    } else if (sg >= 52 && sg < 54) {    // root2 region: kr in [0,32)
        int kr = k - 832;
        f0 = root2[kr * C2 + n];       f1 = root2[(kr + 1) * C2 + n];
        f2 = root2[(kr + 8) * C2 + n]; f3 = root2[(kr + 9) * C2 + n];
    }
    __nv_bfloat162 lo = __float22bfloat162_rn(make_float2(f0, f1));
    __nv_bfloat162 hi = __float22bfloat162_rn(make_float2(f2, f3));
    g_W2f[t] = make_uint2(*(uint32_t*)&lo, *(uint32_t*)&hi);
}

// ---------------- edge pass 1 ----------------
__global__ void k_edge1(const float* __restrict__ x, const float* __restrict__ ea,
                        const int* __restrict__ src, const int* __restrict__ dst, int E) {
    int e = blockIdx.x * blockDim.x + threadIdx.x;
    if (e >= E) return;
    int wi[4]; float bw[4];
    float2 eav = ((const float2*)ea)[e];
    basis2(eav.x, eav.y, wi, bw);
    float xs = x[src[e]];
    int d = dst[e];
    float* Tp = g_T + d * K2;
#pragma unroll
    for (int i = 0; i < 4; i++) atomicAdd(Tp + wi[i], bw[i] * xs);
    atomicAdd(g_deg + d, 1.f);
}

// ---------------- layer-1 node update (writes bf16 h1, dinv, graph counts) ----------------
__global__ void k_h1(const float* __restrict__ x, const float* __restrict__ W1,
                     const float* __restrict__ root1, const float* __restrict__ b1,
                     const int* __restrict__ batch, int N) {
    int t = blockIdx.x * blockDim.x + threadIdx.x;
    if (t >= N * 16) return;
    int n = t >> 4, c2 = t & 15;
    const float* Tp = g_T + n * K2;
    float a0 = 0.f, a1 = 0.f;
#pragma unroll
    for (int w = 0; w < K2; w++) {
        float tv = Tp[w];
        a0 += tv * W1[w * C1 + 2 * c2];
        a1 += tv * W1[w * C1 + 2 * c2 + 1];
    }
    float dinv = 1.f / fmaxf(g_deg[n], 1.f);
    float xn = x[n];
    float h0 = fmaxf(a0 * dinv + xn * root1[2 * c2]     + b1[2 * c2],     0.f);
    float h1 = fmaxf(a1 * dinv + xn * root1[2 * c2 + 1] + b1[2 * c2 + 1], 0.f);
    __nv_bfloat162 hb = __float22bfloat162_rn(make_float2(h0, h1));
    g_h1b[t] = *(unsigned int*)&hb;
    if (c2 == 0) {
        g_dinv[n] = dinv;
        atomicAdd(&g_cnt[batch[n]], 1.f);
    }
}

// ---------------- edge pass 2: bf16x2 red.global ----------------
__global__ void k_edge2(const float* __restrict__ ea,
                        const int* __restrict__ src, const int* __restrict__ dst, int E) {
    int gt = blockIdx.x * blockDim.x + threadIdx.x;
    int lane = gt & 31;
    int warp = gt >> 5;
    int e = warp * 2 + (lane >> 4);
    int hl = lane & 15;
    if (e >= E) return;
    int s = src[e], d = dst[e];
    float2 eav = ((const float2*)ea)[e];
    int wi[4]; float bw[4];
    basis2(eav.x, eav.y, wi, bw);
    float2 h = __bfloat1622float2(*(__nv_bfloat162*)&g_h1b[s * 16 + hl]);
    unsigned int* base = g_Sb + d * 400 + hl;
#pragma unroll
    for (int i = 0; i < 4; i++) {
        __nv_bfloat162 v = __float22bfloat162_rn(make_float2(bw[i] * h.x, bw[i] * h.y));
        red_bf162(base + wi[i] * 16, *(unsigned int*)&v);
    }
}

// ---------------- fused GEMM (HMMA) + layer-2 epilogue + pooling ----------------
// C[N,64] = (S/deg)[N,800] @ W2 + h1[N,32] @ root2 ; h2 = relu(C + b2); pool += h2
// block: 256 thr / 8 warps; tile M=128 x N=64; 14 K-chunks of 64 (chunk 13 = h1/root2)
__global__ void __launch_bounds__(256) k_gemm_mma(const float* __restrict__ b2,
                                                  const int* __restrict__ batch, int N) {
    __shared__ __align__(16) uint8_t smA[16384];
    int tid = threadIdx.x;
    int warp = tid >> 5, lane = tid & 31;
    int gid = lane >> 2, tig = lane & 3;
    int rowBase = blockIdx.x * 128;
    uint32_t smA_b = smem_u32(smA);

    float acc[8][4];
#pragma unroll
    for (int g = 0; g < 8; g++)
#pragma unroll
        for (int j = 0; j < 4; j++) acc[g][j] = 0.f;

    for (int c0 = 0; c0 < 14; c0++) {
        // ---- fill A tile (128 rows x 64 bf16), xor-swizzled 16B chunks ----
#pragma unroll
        for (int j = 0; j < 4; j++) {
            int c = tid + 256 * j;          // 0..1023
            int row = c >> 3, ch = c & 7;
            int grow = rowBase + row;
            uint4 v = make_uint4(0u, 0u, 0u, 0u);
            if (grow < N) {
                if (c0 < 13) {
                    int off = c0 * 32 + ch * 4;
                    if (off < 400) {
                        v = *(const uint4*)(g_Sb + grow * 400 + off);
                        float s = g_dinv[grow];
                        v.x = scale_bf162(v.x, s); v.y = scale_bf162(v.y, s);
                        v.z = scale_bf162(v.z, s); v.w = scale_bf162(v.w, s);
                    }
                } else if (ch < 4) {
                    v = *(const uint4*)(g_h1b + grow * 16 + ch * 4);
                }
            }
            *(uint4*)(smA + row * 128 + ((ch ^ (row & 7)) << 4)) = v;
        }
        __syncthreads();
        // ---- 4 ksteps of m16n8k16 ----
#pragma unroll
        for (int ks = 0; ks < 4; ks++) {
            int mrow = warp * 16 + (lane & 15);
            uint32_t addr = smA_b + mrow * 128 + (((ks * 2 + (lane >> 4)) ^ (mrow & 7)) << 4);
            uint32_t a0, a1, a2, a3;
            ldmatrix_x4(a0, a1, a2, a3, addr);
            int sg = c0 * 4 + ks;
            const uint2* bf = g_W2f + (sg << 8) + lane;
#pragma unroll
            for (int ng = 0; ng < 8; ng++) {
                uint2 b = bf[ng << 5];
                mma_bf16(acc[ng], a0, a1, a2, a3, b.x, b.y);
            }
        }
        __syncthreads();
    }

    // ---- epilogue: +b2, relu, pool reduction ----
    int r0 = rowBase + warp * 16 + gid;
    int r1 = r0 + 8;
    int bt0 = (r0 < N) ? batch[r0] : -1;
    int bt1 = (r1 < N) ? batch[r1] : -1;
#pragma unroll
    for (int ng = 0; ng < 8; ng++) {
        int col = ng * 8 + tig * 2;
        float2 bb = *(const float2*)(b2 + col);
        if (bt0 >= 0) {
            red_f32(g_pool + bt0 * C2 + col,     fmaxf(acc[ng][0] + bb.x, 0.f));
            red_f32(g_pool + bt0 * C2 + col + 1, fmaxf(acc[ng][1] + bb.y, 0.f));
        }
        if (bt1 >= 0) {
            red_f32(g_pool + bt1 * C2 + col,     fmaxf(acc[ng][2] + bb.x, 0.f));
            red_f32(g_pool + bt1 * C2 + col + 1, fmaxf(acc[ng][3] + bb.y, 0.f));
        }
    }
}

// ---------------- head MLP + log_softmax ----------------
__global__ void k_mlp(const float* __restrict__ Wf1, const float* __restrict__ bf1,
                      const float* __restrict__ Wf2, const float* __restrict__ bf2,
                      float* __restrict__ out) {
    int b = blockIdx.x;
    int j = threadIdx.x;
    __shared__ float gs[C2];
    __shared__ float ts[128];
    __shared__ float lg[10];
    if (j < C2) gs[j] = g_pool[b * C2 + j] / fmaxf(g_cnt[b], 1.f);
    __syncthreads();
    float t = bf1[j];
#pragma unroll
    for (int k = 0; k < C2; k++) t += gs[k] * Wf1[k * 128 + j];
    ts[j] = fmaxf(t, 0.f);
    __syncthreads();
    if (j < 10) {
        float a = bf2[j];
#pragma unroll
        for (int q = 0; q < 128; q++) a += ts[q] * Wf2[q * 10 + j];
        lg[j] = a;
    }
    __syncthreads();
    if (j == 0) {
        float m = lg[0];
#pragma unroll
        for (int q = 1; q < 10; q++) m = fmaxf(m, lg[q]);
        float s = 0.f;
#pragma unroll
        for (int q = 0; q < 10; q++) s += expf(lg[q] - m);
        float l = logf(s) + m;
#pragma unroll
        for (int q = 0; q < 10; q++) out[b * 10 + q] = lg[q] - l;
    }
}

// ---------------- launch ----------------
extern "C" void kernel_launch(void* const* d_in, const int* in_sizes, int n_in,
                              void* d_out, int out_size) {
    const float* x     = (const float*)d_in[0];
    const float* ea    = (const float*)d_in[1];
    const float* W1    = (const float*)d_in[2];
    const float* root1 = (const float*)d_in[3];
    const float* b1    = (const float*)d_in[4];
    const float* W2    = (const float*)d_in[5];
    const float* root2 = (const float*)d_in[6];
    const float* b2    = (const float*)d_in[7];
    const float* Wf1   = (const float*)d_in[8];
    const float* bf1   = (const float*)d_in[9];
    const float* Wf2   = (const float*)d_in[10];
    const float* bf2   = (const float*)d_in[11];
    const int*   ei    = (const int*)d_in[12];
    const int*   batch = (const int*)d_in[13];

    int N = in_sizes[0];
    int E = in_sizes[1] / 2;
    const int* src = ei;
    const int* dst = ei + E;
    float* out = (float*)d_out;

    k_zero<<<2048, 256>>>(N);
    k_prepB<<<(56 * 8 * 32 + 255) / 256, 256>>>(W2, root2);
    k_edge1<<<(E + 255) / 256, 256>>>(x, ea, src, dst, E);
    k_h1<<<(N * 16 + 255) / 256, 256>>>(x, W1, root1, b1, batch, N);
    k_edge2<<<(E * 16 + 255) / 256, 256>>>(ea, src, dst, E);
    k_gemm_mma<<<(N + 127) / 128, 256>>>(b2, batch, N);
    k_mlp<<<NG, 128>>>(Wf1, bf1, Wf2, bf2, out);
}